// round 13
// baseline (speedup 1.0000x reference)
#include <cuda_runtime.h>
#include <cuda_fp16.h>
#include <math.h>

// Problem constants
#define B 4
#define T 4096
#define E 204
#define H 64
#define NROWS (B*T)          // 16384
#define SCALE2 (0.07001400420140049f * 1.4426950408889634f)  // 1/sqrt(204) * log2(e)

// QKV tiling: K padded to 208 = 13 chunks of 16
#define NQK 192              // Q|K|V output cols
#define WROW 104             // u32 per W16 row (208 dims / 2)

// Attention tiling
#define QT 128               // queries per block (4 warps x 32 rows)
#define KT2 64               // keys per smem tile
#define CH 512               // split-K chunk
#define NCH (T/CH)           // 8
#define NST (T/QT)           // 32
#define NBLK 144             // active blocks per batch

// attn smem (u32): 3 K/V buffers of 5120 (K 2560 | V 2560), Q at 15360 [128][36]
#define QST_OFF 15360
#define ATTN_SMEM_B ((QST_OFF + 128*36) * 4)   // 79872 bytes

// ---------------- static scratch (no allocation allowed) ----------------
__device__ unsigned g_W16h[NQK*WROW];            // W^T hi fp16x2, B-frag interleave
__device__ unsigned g_W16l[NQK*WROW];            // W^T lo
__device__ unsigned g_Q16[(size_t)NROWS*32];     // Q fp16x2, pre-scaled by SCALE2
__device__ unsigned g_K16[(size_t)NROWS*32];     // K fp16x2, dim-interleaved
__device__ unsigned g_Vt16[(size_t)B*H*(T/2)];   // V^T fp16x2 [b][h][t], t-interleaved
__device__ unsigned g_Op16[(size_t)B*NST*NCH*QT*32];  // partial O, fp16x2
__device__ float g_Lp[B*NST*NCH*QT];             // partial row-sum (fp32)
__device__ unsigned g_cnt[B*NST];                // strip arrival counters (zero-init)

// ---------------- helpers ----------------
__device__ __forceinline__ void mma_f16(float* d, const unsigned* a,
                                        unsigned b0, unsigned b1) {
    asm volatile(
        "mma.sync.aligned.m16n8k16.row.col.f32.f16.f16.f32 "
        "{%0,%1,%2,%3}, {%4,%5,%6,%7}, {%8,%9}, {%0,%1,%2,%3};\n"
        : "+f"(d[0]), "+f"(d[1]), "+f"(d[2]), "+f"(d[3])
        : "r"(a[0]), "r"(a[1]), "r"(a[2]), "r"(a[3]), "r"(b0), "r"(b1));
}

__device__ __forceinline__ unsigned pack_h2(float a, float b) {
    __half2 h = __floats2half2_rn(a, b);
    return *reinterpret_cast<unsigned*>(&h);
}

// fp16 hi/lo split of a float pair, packed fp16x2
__device__ __forceinline__ void split2(float a, float b, unsigned &hi, unsigned &lo) {
    __half2 h2 = __floats2half2_rn(a, b);
    float ar = a - __half2float(h2.x);
    float br = b - __half2float(h2.y);
    __half2 l2 = __floats2half2_rn(ar, br);
    hi = *reinterpret_cast<unsigned*>(&h2);
    lo = *reinterpret_cast<unsigned*>(&l2);
}

__device__ __forceinline__ unsigned h2exp2(unsigned x) {
    unsigned y;
    asm("ex2.approx.f16x2 %0, %1;" : "=r"(y) : "r"(x));
    return y;
}

__device__ __forceinline__ unsigned smem_u32(const void* p) {
    unsigned a;
    asm("{ .reg .u64 t; cvta.to.shared.u64 t, %1; cvt.u32.u64 %0, t; }" : "=r"(a) : "l"(p));
    return a;
}

__device__ __forceinline__ void cp16(unsigned dst, const void* src) {
    asm volatile("cp.async.cg.shared.global [%0], [%1], 16;" :: "r"(dst), "l"(src));
}
#define CP_COMMIT()  asm volatile("cp.async.commit_group;" ::: "memory")
#define CP_WAIT_ALL() asm volatile("cp.async.wait_group 0;" ::: "memory")
#define CP_WAIT_1()  asm volatile("cp.async.wait_group 1;" ::: "memory")

// u32 slot within a row for even dim d: per-16 group [p0 p4 p1 p5 p2 p6 p3 p7]
__device__ __forceinline__ int ileave_u32(int d) {
    return (d >> 4) * 8 + ((d & 7) >> 1) * 2 + (((d & 15) >= 8) ? 1 : 0);
}

// =========== Pass 0: W^T -> fp16 hi/lo, B-fragment interleaved ===========
__global__ __launch_bounds__(256) void wt_split(
    const float* __restrict__ Wq, const float* __restrict__ Wk,
    const float* __restrict__ Wv)
{
    int idx = blockIdx.x * 256 + threadIdx.x;
    if (idx >= NQK * WROW) return;
    int n = idx / WROW, cpos = idx % WROW;
    int ks = cpos >> 3, cw = cpos & 7;
    int d0 = 16 * ks + ((cw >> 1) << 1) + ((cw & 1) ? 8 : 0);
    const float* W = (n < 64) ? Wq : (n < 128) ? Wk : Wv;
    int col = n & 63;
    float v0 = (d0     < E) ? W[d0 * H + col]       : 0.f;
    float v1 = (d0 + 1 < E) ? W[(d0 + 1) * H + col] : 0.f;
    unsigned hi, lo;
    split2(v0, v1, hi, lo);
    g_W16h[n * WROW + cpos] = hi;
    g_W16l[n * WROW + cpos] = lo;
}

// ============== Pass 1: QKV projection via 3-term fp16 m16n8k16 ============
__global__ __launch_bounds__(256) void qkv_mma(const float* __restrict__ x)
{
    __shared__ unsigned qsm[4608];        // 18 KB, multi-purpose
    unsigned* s_wh = qsm;                 // [192][8]
    unsigned* s_wl = qsm + 1536;          // [192][8]
    unsigned* s_xh = qsm + 3072;          // [64][12]
    unsigned* s_xl = qsm + 3840;          // [64][12]

    const int tid = threadIdx.x;
    const int w = tid >> 5, lane = tid & 31;
    const int g = lane >> 2, j = lane & 3;
    const int rw = w >> 1, ch = w & 1;
    const int row0 = blockIdx.x * 64;
    const int r0 = rw * 16 + g, r1 = r0 + 8;

    float acc[12][4];
    #pragma unroll
    for (int nt = 0; nt < 12; nt++)
        #pragma unroll
        for (int i = 0; i < 4; i++) acc[nt][i] = 0.f;

    for (int kc = 0; kc < 208; kc += 16) {
        __syncthreads();
        #pragma unroll
        for (int i = 0; i < 2; i++) {
            int u = tid + i * 256;               // 0..511
            int r = u >> 3, cc = u & 7;
            int k = kc + 2 * cc;
            float v0 = 0.f, v1 = 0.f;
            if (k + 1 < E) {
                float2 t = *(const float2*)&x[(size_t)(row0 + r) * E + k];
                v0 = t.x; v1 = t.y;
            } else if (k < E) {
                v0 = x[(size_t)(row0 + r) * E + k];
            }
            unsigned hi, lo;
            split2(v0, v1, hi, lo);
            s_xh[r * 12 + cc] = hi;
            s_xl[r * 12 + cc] = lo;
        }
        int ko = kc >> 1;
        #pragma unroll
        for (int i = 0; i < 3; i++) {
            int idx = tid + i * 256;             // 0..767
            int a = idx >= 384 ? 1 : 0;
            int rem = idx - a * 384;
            int n = rem >> 1, half = rem & 1;
            const unsigned* src = (a ? g_W16l : g_W16h) + n * WROW + ko + half * 4;
            unsigned* dst = (a ? s_wl : s_wh) + n * 8 + half * 4;
            *(uint4*)dst = *(const uint4*)src;
        }
        __syncthreads();

        unsigned ah[4], al[4];
        ah[0] = s_xh[r0*12 + j];     ah[1] = s_xh[r1*12 + j];
        ah[2] = s_xh[r0*12 + j + 4]; ah[3] = s_xh[r1*12 + j + 4];
        al[0] = s_xl[r0*12 + j];     al[1] = s_xl[r1*12 + j];
        al[2] = s_xl[r0*12 + j + 4]; al[3] = s_xl[r1*12 + j + 4];
        #pragma unroll
        for (int nt = 0; nt < 12; nt++) {
            int rb = ch * 96 + nt * 8 + g;
            uint2 bh = *(uint2*)&s_wh[rb * 8 + 2 * j];
            uint2 bl = *(uint2*)&s_wl[rb * 8 + 2 * j];
            mma_f16(acc[nt], ah, bh.x, bh.y);
            mma_f16(acc[nt], al, bh.x, bh.y);
            mma_f16(acc[nt], ah, bl.x, bl.y);
        }
    }
    __syncthreads();   // reuse qsm as V staging

    float (*Vsm)[66] = (float(*)[66])qsm;
    const int b = row0 >> 12;
    const int t0 = row0 & (T - 1);
    const size_t R0g = row0 + r0, R1g = row0 + r1;

    #pragma unroll
    for (int nt = 0; nt < 12; nt++) {
        int c0 = ch * 96 + nt * 8 + 2 * j;
        float2 v0 = make_float2(acc[nt][0], acc[nt][1]);
        float2 v1 = make_float2(acc[nt][2], acc[nt][3]);
        if (c0 < 64) {
            g_Q16[R0g * 32 + (c0 >> 1)] = pack_h2(v0.x * SCALE2, v0.y * SCALE2);
            g_Q16[R1g * 32 + (c0 >> 1)] = pack_h2(v1.x * SCALE2, v1.y * SCALE2);
        } else if (c0 < 128) {
            int ui = ileave_u32(c0 - 64);
            g_K16[R0g * 32 + ui] = pack_h2(v0.x, v0.y);
            g_K16[R1g * 32 + ui] = pack_h2(v1.x, v1.y);
        } else {
            *(float2*)&Vsm[r0][c0 - 128] = v0;
            *(float2*)&Vsm[r1][c0 - 128] = v1;
        }
    }
    __syncthreads();
    {
        int tl2 = (tid & 31) * 2;
        int h0 = (tid >> 5) * 8;
        #pragma unroll
        for (int i = 0; i < 8; i++) {
            int h = h0 + i;
            unsigned pv = pack_h2(Vsm[tl2][h], Vsm[tl2 + 1][h]);
            int t = t0 + tl2;
            size_t ui = ((size_t)b * H + h) * (T / 2) + ileave_u32(t & 15)
                      + ((t >> 4) * 8);
            g_Vt16[ui] = pv;
        }
    }
}

// ---------------- attention QK phase ----------------
__device__ __forceinline__ void qk_phase(
    const unsigned* __restrict__ Ks, const unsigned* __restrict__ Qst,
    int rA0, int rA1, int rB0, int rB1, int g, int j,
    float sA[8][4], float sB[8][4])
{
    #pragma unroll
    for (int n = 0; n < 8; n++)
        #pragma unroll
        for (int i = 0; i < 4; i++) { sA[n][i] = 0.f; sB[n][i] = 0.f; }
    #pragma unroll
    for (int ks = 0; ks < 4; ks++) {
        unsigned aA[4], aB[4];
        aA[0] = Qst[rA0 * 36 + 8 * ks + j];
        aA[1] = Qst[rA1 * 36 + 8 * ks + j];
        aA[2] = Qst[rA0 * 36 + 8 * ks + j + 4];
        aA[3] = Qst[rA1 * 36 + 8 * ks + j + 4];
        aB[0] = Qst[rB0 * 36 + 8 * ks + j];
        aB[1] = Qst[rB1 * 36 + 8 * ks + j];
        aB[2] = Qst[rB0 * 36 + 8 * ks + j + 4];
        aB[3] = Qst[rB1 * 36 + 8 * ks + j + 4];
        #pragma unroll
        for (int n = 0; n < 8; n++) {
            uint2 bb = *(const uint2*)&Ks[(n * 8 + g) * 40 + ks * 8 + 2 * j];
            mma_f16(sA[n], aA, bb.x, bb.y);
            mma_f16(sB[n], aB, bb.x, bb.y);
        }
    }
}

// ======= Pass 2: pipelined split-K flash attention + fused combine =========
// 3 smem buffers, prefetch distance 2 (as R12). NEW: last-arriving block per
// query strip (atomic counter) performs the split-K combine inline, hiding the
// old combine kernel + launch gap under remaining attention work.
__global__ __launch_bounds__(128, 2) void attn_f16(float* __restrict__ out)
{
    // ---- heavy-first block mapping ----
    const int b = blockIdx.x;
    const int f = blockIdx.y;
    int s, c;
    if (f < 120) {               // full blocks (8 tiles)
        int rem = f, cc = 0;
        while (rem >= 29 - 4 * cc) { rem -= 29 - 4 * cc; cc++; }
        c = cc;
        s = 4 * c + 3 + rem;
    } else {                     // partial diagonal blocks, heaviest first
        int p = f - 120;
        int gq = p >> 3;
        int i = p & 7;
        s = 4 * i + (2 - gq);
        c = i;
    }
    const int qs = s * QT;
    const int kstart = c * CH;
    const int kend = min(kstart + CH, qs + QT);
    const int nt = (kend - kstart) >> 6;     // 2..8

    extern __shared__ unsigned sm[];
    const unsigned sb = smem_u32(sm);
    const unsigned* Qst = sm + QST_OFF;      // [128][36]

    const int tid = threadIdx.x;
    const int w = tid >> 5;
    const int lane = tid & 31;
    const int g = lane >> 2;
    const int j = lane & 3;
    const int base = w * 32;
    const int rA0 = base + g,  rA1 = rA0 + 8;
    const int rB0 = rA0 + 16,  rB1 = rA0 + 24;

    const size_t kbase = (size_t)b * T;
    const size_t vbase = (size_t)b * H;

    // ---- prologue: Q + tile0 (group 0), tile1 (group 1) ----
    const size_t qrowbase = kbase + qs;
    #pragma unroll
    for (int i = 0; i < 8; i++) {
        int u = tid + i * 128;
        int r = u >> 3, c4 = u & 7;
        cp16(sb + (QST_OFF + r * 36 + c4 * 4) * 4, &g_Q16[(qrowbase + r) * 32 + c4 * 4]);
    }
    #pragma unroll
    for (int i = 0; i < 4; i++) {
        int u = tid + i * 128;
        int r = u >> 3, cc = u & 7;
        unsigned d = sb + (r * 40 + cc * 4) * 4;
        cp16(d,         &g_K16[(kbase + kstart + r) * 32 + cc * 4]);
        cp16(d + 10240, &g_Vt16[(vbase + r) * (T / 2) + (kstart >> 1) + cc * 4]);
    }
    CP_COMMIT();                 // G0: Q + tile0
    #pragma unroll
    for (int i = 0; i < 4; i++) {
        int u = tid + i * 128;
        int r = u >> 3, cc = u & 7;
        unsigned d = sb + (5120 + r * 40 + cc * 4) * 4;
        cp16(d,         &g_K16[(kbase + kstart + 64 + r) * 32 + cc * 4]);
        cp16(d + 10240, &g_Vt16[(vbase + r) * (T / 2) + ((kstart + 64) >> 1) + cc * 4]);
    }
    CP_COMMIT();                 // G1: tile1
    CP_WAIT_1();                 // G0 complete
    __syncthreads();

    float sA[8][4], sB[8][4];
    qk_phase(sm, Qst, rA0, rA1, rB0, rB1, g, j, sA, sB);   // QK(tile0)

    float oA[8][4], oB[8][4], olA[4], olB[4];
    #pragma unroll
    for (int n = 0; n < 8; n++)
        #pragma unroll
        for (int i = 0; i < 4; i++) { oA[n][i] = 0.f; oB[n][i] = 0.f; }
    #pragma unroll
    for (int i = 0; i < 4; i++) { olA[i] = 0.f; olB[i] = 0.f; }

    const int gr0 = qs + rA0;
    const int wmin = qs + base;
    const unsigned ONE2 = 0x3C003C00u;
    unsigned paA[4][4], paB[4][4];

    for (int t = 0; t < nt; t++) {
        const int kt = kstart + t * KT2;
        const bool act = (kt <= wmin + 31);

        // ---- exp/mask (t): register-only ----
        if (act) {
            if (kt + KT2 - 1 > wmin) {
                #pragma unroll
                for (int n = 0; n < 8; n++) {
                    int col = kt + n * 8 + 2 * j;
                    if (col     > gr0     ) sA[n][0] = -1e4f;
                    if (col + 1 > gr0     ) sA[n][1] = -1e4f;
                    if (col     > gr0 +  8) sA[n][2] = -1e4f;
                    if (col + 1 > gr0 +  8) sA[n][3] = -1e4f;
                    if (col     > gr0 + 16) sB[n][0] = -1e4f;
                    if (col + 1 > gr0 + 16) sB[n][1] = -1e4f;
                    if (col     > gr0 + 24) sB[n][2] = -1e4f;
                    if (col + 1 > gr0 + 24) sB[n][3] = -1e4f;
                }
            }
            #pragma unroll
            for (int n = 0; n < 8; n++) {
                int kk = n >> 1, hf = (n & 1) * 2;
                paA[kk][hf]     = h2exp2(pack_h2(sA[n][0], sA[n][1]));
                paA[kk][hf + 1] = h2exp2(pack_h2(sA[n][2], sA[n][3]));
                paB[kk][hf]     = h2exp2(pack_h2(sB[n][0], sB[n][1]));
                paB[kk][hf + 1] = h2exp2(pack_h2(sB[n][2], sB[n][3]));
            }
        }

        if (t + 1 < nt) {
            CP_WAIT_ALL();       // tile t+1 landed
            __syncthreads();
            if (t + 2 < nt) {    // prefetch t+2 into the dead buffer
                int nb = (t + 2) % 3;
                int ktn = kt + 2 * KT2;
                #pragma unroll
                for (int i = 0; i < 4; i++) {
                    int u = tid + i * 128;
                    int r = u >> 3, cc = u & 7;
                    unsigned d = sb + (nb * 5120 + r * 40 + cc * 4) * 4;
                    cp16(d,         &g_K16[(kbase + ktn + r) * 32 + cc * 4]);
                    cp16(d + 10240, &g_Vt16[(vbase + r) * (T / 2) + (ktn >> 1) + cc * 4]);
                }
                CP_COMMIT();
            }
            if (kt + KT2 <= wmin + 31)
                qk_phase(sm + ((t + 1) % 3) * 5120, Qst,
                         rA0, rA1, rB0, rB1, g, j, sA, sB);
        }

        // ---- PV(t) ----
        if (act) {
            const unsigned* Vts = sm + (t % 3) * 5120 + 2560;
            #pragma unroll
            for (int kk = 0; kk < 4; kk++) {
                #pragma unroll
                for (int nn = 0; nn < 8; nn++) {
                    uint2 bb = *(const uint2*)&Vts[(nn * 8 + g) * 40 + kk * 8 + 2 * j];
                    mma_f16(oA[nn], paA[kk], bb.x, bb.y);
                    mma_f16(oB[nn], paB[kk], bb.x, bb.y);
                }
                mma_f16(olA, paA[kk], ONE2, ONE2);
                mma_f16(olB, paB[kk], ONE2, ONE2);
            }
        }
    }

    // ---- write partials ----
    size_t pbase = (((size_t)(b * NST + s) * NCH + c) * QT);
    #pragma unroll
    for (int n = 0; n < 8; n++) {
        g_Op16[(pbase + rA0) * 32 + n * 4 + j] = pack_h2(oA[n][0], oA[n][1]);
        g_Op16[(pbase + rA1) * 32 + n * 4 + j] = pack_h2(oA[n][2], oA[n][3]);
        g_Op16[(pbase + rB0) * 32 + n * 4 + j] = pack_h2(oB[n][0], oB[n][1]);
        g_Op16[(pbase + rB1) * 32 + n * 4 + j] = pack_h2(oB[n][2], oB[n][3]);
    }
    if (j == 0) {
        g_Lp[pbase + rA0] = olA[0];
        g_Lp[pbase + rA1] = olA[2];
        g_Lp[pbase + rB0] = olB[0];
        g_Lp[pbase + rB1] = olB[2];
    }

    // ---- fused combine: last block of strip (b,s) reduces it ----
    __threadfence();
    __shared__ unsigned s_old;
    if (tid == 0) s_old = atomicAdd(&g_cnt[b * NST + s], 1u);
    __syncthreads();
    if (s_old != (unsigned)(s >> 2)) return;   // nchunks-1 = s/4

    if (tid == 0) g_cnt[b * NST + s] = 0;      // reset for next graph replay
    __threadfence();                            // acquire partials

    const int nch = (s >> 2) + 1;
    const int qq = tid >> 2;                    // 0..31: query within pass
    const int dq = tid & 3;                     // dim quarter (16 dims)
    const size_t strip = ((size_t)(b * NST + s) * NCH) * QT;

    #pragma unroll 1
    for (int p = 0; p < 4; p++) {
        int ql = p * 32 + qq;
        size_t qb = strip + ql;
        float L = 0.f;
        for (int cc = 0; cc < nch; cc++) L += g_Lp[qb + (size_t)cc * QT];
        float inv = 1.0f / L;

        float acc[16];
        #pragma unroll
        for (int i = 0; i < 16; i++) acc[i] = 0.f;
        for (int cc = 0; cc < nch; cc++) {
            const unsigned* src = &g_Op16[(qb + (size_t)cc * QT) * 32 + dq * 8];
            uint4 v0 = *(const uint4*)src;
            uint4 v1 = *(const uint4*)(src + 4);
            const unsigned vv[8] = { v0.x, v0.y, v0.z, v0.w, v1.x, v1.y, v1.z, v1.w };
            #pragma unroll
            for (int i = 0; i < 8; i++) {
                float2 ff = __half22float2(*reinterpret_cast<const __half2*>(&vv[i]));
                acc[2*i]   += ff.x;
                acc[2*i+1] += ff.y;
            }
        }
        float* dst = out + ((size_t)(b * T + qs + ql)) * H + dq * 16;
        #pragma unroll
        for (int i = 0; i < 4; i++) {
            *(float4*)(dst + 4 * i) = make_float4(
                acc[4*i] * inv, acc[4*i+1] * inv,
                acc[4*i+2] * inv, acc[4*i+3] * inv);
        }
    }
}

// ================================ launcher ==================================
extern "C" void kernel_launch(void* const* d_in, const int* in_sizes, int n_in,
                              void* d_out, int out_size)
{
    const float* x  = (const float*)d_in[0];
    const float* Wq = (const float*)d_in[1];
    const float* Wk = (const float*)d_in[2];
    const float* Wv = (const float*)d_in[3];

    cudaFuncSetAttribute(attn_f16, cudaFuncAttributeMaxDynamicSharedMemorySize,
                         ATTN_SMEM_B);

    wt_split<<<(NQK * WROW + 255) / 256, 256>>>(Wq, Wk, Wv);
    qkv_mma<<<NROWS / 64, 256>>>(x);
    attn_f16<<<dim3(B, NBLK), 128, ATTN_SMEM_B>>>((float*)d_out);
}

// round 14
// speedup vs baseline: 1.1416x; 1.1416x over previous
#include <cuda_runtime.h>
#include <cuda_fp16.h>
#include <math.h>

// Problem constants
#define B 4
#define T 4096
#define E 204
#define H 64
#define NROWS (B*T)          // 16384
#define SCALE2 (0.07001400420140049f * 1.4426950408889634f)  // 1/sqrt(204) * log2(e)

// QKV tiling: K padded to 208 = 13 chunks of 16
#define NQK 192              // Q|K|V output cols
#define WROW 104             // u32 per W16 row (208 dims / 2)

// Attention tiling
#define QT 128               // queries per block (4 warps x 32 rows)
#define KT2 64               // keys per smem tile
#define CH 512               // split-K chunk
#define NCH (T/CH)           // 8
#define NST (T/QT)           // 32
#define NBLK 144             // active blocks per batch

// attn smem (u32): 3 K/V buffers of 5120 (K 2560 | V 2560), Q at 15360 [128][36]
#define QST_OFF 15360
#define ATTN_SMEM_B ((QST_OFF + 128*36) * 4)   // 79872 bytes

// ---------------- static scratch (no allocation allowed) ----------------
__device__ unsigned g_W16h[NQK*WROW];            // W^T hi fp16x2, B-frag interleave
__device__ unsigned g_W16l[NQK*WROW];            // W^T lo
__device__ unsigned g_Q16[(size_t)NROWS*32];     // Q fp16x2, pre-scaled by SCALE2
__device__ unsigned g_K16[(size_t)NROWS*32];     // K fp16x2, dim-interleaved
__device__ unsigned g_Vt16[(size_t)B*H*(T/2)];   // V^T fp16x2 [b][h][t], t-interleaved
__device__ float g_L32[NROWS];                   // fp32 row-sum accumulator

// ---------------- helpers ----------------
__device__ __forceinline__ void mma_f16(float* d, const unsigned* a,
                                        unsigned b0, unsigned b1) {
    asm volatile(
        "mma.sync.aligned.m16n8k16.row.col.f32.f16.f16.f32 "
        "{%0,%1,%2,%3}, {%4,%5,%6,%7}, {%8,%9}, {%0,%1,%2,%3};\n"
        : "+f"(d[0]), "+f"(d[1]), "+f"(d[2]), "+f"(d[3])
        : "r"(a[0]), "r"(a[1]), "r"(a[2]), "r"(a[3]), "r"(b0), "r"(b1));
}

__device__ __forceinline__ unsigned pack_h2(float a, float b) {
    __half2 h = __floats2half2_rn(a, b);
    return *reinterpret_cast<unsigned*>(&h);
}

// fp16 hi/lo split of a float pair, packed fp16x2
__device__ __forceinline__ void split2(float a, float b, unsigned &hi, unsigned &lo) {
    __half2 h2 = __floats2half2_rn(a, b);
    float ar = a - __half2float(h2.x);
    float br = b - __half2float(h2.y);
    __half2 l2 = __floats2half2_rn(ar, br);
    hi = *reinterpret_cast<unsigned*>(&h2);
    lo = *reinterpret_cast<unsigned*>(&l2);
}

__device__ __forceinline__ unsigned h2exp2(unsigned x) {
    unsigned y;
    asm("ex2.approx.f16x2 %0, %1;" : "=r"(y) : "r"(x));
    return y;
}

__device__ __forceinline__ unsigned smem_u32(const void* p) {
    unsigned a;
    asm("{ .reg .u64 t; cvta.to.shared.u64 t, %1; cvt.u32.u64 %0, t; }" : "=r"(a) : "l"(p));
    return a;
}

__device__ __forceinline__ void cp16(unsigned dst, const void* src) {
    asm volatile("cp.async.cg.shared.global [%0], [%1], 16;" :: "r"(dst), "l"(src));
}
#define CP_COMMIT()  asm volatile("cp.async.commit_group;" ::: "memory")
#define CP_WAIT_ALL() asm volatile("cp.async.wait_group 0;" ::: "memory")
#define CP_WAIT_1()  asm volatile("cp.async.wait_group 1;" ::: "memory")

// u32 slot within a row for even dim d: per-16 group [p0 p4 p1 p5 p2 p6 p3 p7]
__device__ __forceinline__ int ileave_u32(int d) {
    return (d >> 4) * 8 + ((d & 7) >> 1) * 2 + (((d & 15) >= 8) ? 1 : 0);
}

// ============ Pass -1: zero d_out (poisoned) + L accumulators ==============
__global__ __launch_bounds__(256) void zero_kernel(float* __restrict__ out)
{
    int idx = blockIdx.x * 256 + threadIdx.x;        // 262144 float4
    ((float4*)out)[idx] = make_float4(0.f, 0.f, 0.f, 0.f);
    if (idx < NROWS) g_L32[idx] = 0.f;
}

// =========== Pass 0: W^T -> fp16 hi/lo, B-fragment interleaved ==============
// n-major indexing: consecutive threads read consecutive W columns (coalesced).
__global__ __launch_bounds__(256) void wt_split(
    const float* __restrict__ Wq, const float* __restrict__ Wk,
    const float* __restrict__ Wv)
{
    int idx = blockIdx.x * 256 + threadIdx.x;
    if (idx >= NQK * WROW) return;
    int cpos = idx / NQK, n = idx % NQK;
    int ks = cpos >> 3, cw = cpos & 7;
    int d0 = 16 * ks + ((cw >> 1) << 1) + ((cw & 1) ? 8 : 0);
    const float* W = (n < 64) ? Wq : (n < 128) ? Wk : Wv;
    int col = n & 63;
    float v0 = (d0     < E) ? W[d0 * H + col]       : 0.f;
    float v1 = (d0 + 1 < E) ? W[(d0 + 1) * H + col] : 0.f;
    unsigned hi, lo;
    split2(v0, v1, hi, lo);
    g_W16h[n * WROW + cpos] = hi;
    g_W16l[n * WROW + cpos] = lo;
}

// ============== Pass 1: QKV projection via 3-term fp16 m16n8k16 ============
__global__ __launch_bounds__(256) void qkv_mma(const float* __restrict__ x)
{
    __shared__ unsigned qsm[4608];        // 18 KB, multi-purpose
    unsigned* s_wh = qsm;                 // [192][8]
    unsigned* s_wl = qsm + 1536;          // [192][8]
    unsigned* s_xh = qsm + 3072;          // [64][12]
    unsigned* s_xl = qsm + 3840;          // [64][12]

    const int tid = threadIdx.x;
    const int w = tid >> 5, lane = tid & 31;
    const int g = lane >> 2, j = lane & 3;
    const int rw = w >> 1, ch = w & 1;
    const int row0 = blockIdx.x * 64;
    const int r0 = rw * 16 + g, r1 = r0 + 8;

    float acc[12][4];
    #pragma unroll
    for (int nt = 0; nt < 12; nt++)
        #pragma unroll
        for (int i = 0; i < 4; i++) acc[nt][i] = 0.f;

    for (int kc = 0; kc < 208; kc += 16) {
        __syncthreads();
        #pragma unroll
        for (int i = 0; i < 2; i++) {
            int u = tid + i * 256;               // 0..511
            int r = u >> 3, cc = u & 7;
            int k = kc + 2 * cc;
            float v0 = 0.f, v1 = 0.f;
            if (k + 1 < E) {
                float2 t = *(const float2*)&x[(size_t)(row0 + r) * E + k];
                v0 = t.x; v1 = t.y;
            } else if (k < E) {
                v0 = x[(size_t)(row0 + r) * E + k];
            }
            unsigned hi, lo;
            split2(v0, v1, hi, lo);
            s_xh[r * 12 + cc] = hi;
            s_xl[r * 12 + cc] = lo;
        }
        int ko = kc >> 1;
        #pragma unroll
        for (int i = 0; i < 3; i++) {
            int idx = tid + i * 256;             // 0..767
            int a = idx >= 384 ? 1 : 0;
            int rem = idx - a * 384;
            int n = rem >> 1, half = rem & 1;
            const unsigned* src = (a ? g_W16l : g_W16h) + n * WROW + ko + half * 4;
            unsigned* dst = (a ? s_wl : s_wh) + n * 8 + half * 4;
            *(uint4*)dst = *(const uint4*)src;
        }
        __syncthreads();

        unsigned ah[4], al[4];
        ah[0] = s_xh[r0*12 + j];     ah[1] = s_xh[r1*12 + j];
        ah[2] = s_xh[r0*12 + j + 4]; ah[3] = s_xh[r1*12 + j + 4];
        al[0] = s_xl[r0*12 + j];     al[1] = s_xl[r1*12 + j];
        al[2] = s_xl[r0*12 + j + 4]; al[3] = s_xl[r1*12 + j + 4];
        #pragma unroll
        for (int nt = 0; nt < 12; nt++) {
            int rb = ch * 96 + nt * 8 + g;
            uint2 bh = *(uint2*)&s_wh[rb * 8 + 2 * j];
            uint2 bl = *(uint2*)&s_wl[rb * 8 + 2 * j];
            mma_f16(acc[nt], ah, bh.x, bh.y);
            mma_f16(acc[nt], al, bh.x, bh.y);
            mma_f16(acc[nt], ah, bl.x, bl.y);
        }
    }
    __syncthreads();   // reuse qsm as V staging

    float (*Vsm)[66] = (float(*)[66])qsm;
    const int b = row0 >> 12;
    const int t0 = row0 & (T - 1);
    const size_t R0g = row0 + r0, R1g = row0 + r1;

    #pragma unroll
    for (int nt = 0; nt < 12; nt++) {
        int c0 = ch * 96 + nt * 8 + 2 * j;
        float2 v0 = make_float2(acc[nt][0], acc[nt][1]);
        float2 v1 = make_float2(acc[nt][2], acc[nt][3]);
        if (c0 < 64) {
            g_Q16[R0g * 32 + (c0 >> 1)] = pack_h2(v0.x * SCALE2, v0.y * SCALE2);
            g_Q16[R1g * 32 + (c0 >> 1)] = pack_h2(v1.x * SCALE2, v1.y * SCALE2);
        } else if (c0 < 128) {
            int ui = ileave_u32(c0 - 64);
            g_K16[R0g * 32 + ui] = pack_h2(v0.x, v0.y);
            g_K16[R1g * 32 + ui] = pack_h2(v1.x, v1.y);
        } else {
            *(float2*)&Vsm[r0][c0 - 128] = v0;
            *(float2*)&Vsm[r1][c0 - 128] = v1;
        }
    }
    __syncthreads();
    {
        int tl2 = (tid & 31) * 2;
        int h0 = (tid >> 5) * 8;
        #pragma unroll
        for (int i = 0; i < 8; i++) {
            int h = h0 + i;
            unsigned pv = pack_h2(Vsm[tl2][h], Vsm[tl2 + 1][h]);
            int t = t0 + tl2;
            size_t ui = ((size_t)b * H + h) * (T / 2) + ileave_u32(t & 15)
                      + ((t >> 4) * 8);
            g_Vt16[ui] = pv;
        }
    }
}

// ---------------- attention QK phase ----------------
__device__ __forceinline__ void qk_phase(
    const unsigned* __restrict__ Ks, const unsigned* __restrict__ Qst,
    int rA0, int rA1, int rB0, int rB1, int g, int j,
    float sA[8][4], float sB[8][4])
{
    #pragma unroll
    for (int n = 0; n < 8; n++)
        #pragma unroll
        for (int i = 0; i < 4; i++) { sA[n][i] = 0.f; sB[n][i] = 0.f; }
    #pragma unroll
    for (int ks = 0; ks < 4; ks++) {
        unsigned aA[4], aB[4];
        aA[0] = Qst[rA0 * 36 + 8 * ks + j];
        aA[1] = Qst[rA1 * 36 + 8 * ks + j];
        aA[2] = Qst[rA0 * 36 + 8 * ks + j + 4];
        aA[3] = Qst[rA1 * 36 + 8 * ks + j + 4];
        aB[0] = Qst[rB0 * 36 + 8 * ks + j];
        aB[1] = Qst[rB1 * 36 + 8 * ks + j];
        aB[2] = Qst[rB0 * 36 + 8 * ks + j + 4];
        aB[3] = Qst[rB1 * 36 + 8 * ks + j + 4];
        #pragma unroll
        for (int n = 0; n < 8; n++) {
            uint2 bb = *(const uint2*)&Ks[(n * 8 + g) * 40 + ks * 8 + 2 * j];
            mma_f16(sA[n], aA, bb.x, bb.y);
            mma_f16(sB[n], aB, bb.x, bb.y);
        }
    }
}

// ====== Pass 2: pipelined split-K flash attention, fp32 REDG epilogue ======
// Identical mainloop to R12 (3 buffers, prefetch distance 2). Epilogue
// atomically accumulates fp32 O into d_out and l into g_L32 (no partials,
// no combine kernel).
__global__ __launch_bounds__(128, 2) void attn_f16(float* __restrict__ out)
{
    // ---- heavy-first block mapping ----
    const int b = blockIdx.x;
    const int f = blockIdx.y;
    int s, c;
    if (f < 120) {               // full blocks (8 tiles)
        int rem = f, cc = 0;
        while (rem >= 29 - 4 * cc) { rem -= 29 - 4 * cc; cc++; }
        c = cc;
        s = 4 * c + 3 + rem;
    } else {                     // partial diagonal blocks, heaviest first
        int p = f - 120;
        int gq = p >> 3;
        int i = p & 7;
        s = 4 * i + (2 - gq);
        c = i;
    }
    const int qs = s * QT;
    const int kstart = c * CH;
    const int kend = min(kstart + CH, qs + QT);
    const int nt = (kend - kstart) >> 6;     // 2..8

    extern __shared__ unsigned sm[];
    const unsigned sb = smem_u32(sm);
    const unsigned* Qst = sm + QST_OFF;      // [128][36]

    const int tid = threadIdx.x;
    const int w = tid >> 5;
    const int lane = tid & 31;
    const int g = lane >> 2;
    const int j = lane & 3;
    const int base = w * 32;
    const int rA0 = base + g,  rA1 = rA0 + 8;
    const int rB0 = rA0 + 16,  rB1 = rA0 + 24;

    const size_t kbase = (size_t)b * T;
    const size_t vbase = (size_t)b * H;

    // ---- prologue: Q + tile0 (group 0), tile1 (group 1) ----
    const size_t qrowbase = kbase + qs;
    #pragma unroll
    for (int i = 0; i < 8; i++) {
        int u = tid + i * 128;
        int r = u >> 3, c4 = u & 7;
        cp16(sb + (QST_OFF + r * 36 + c4 * 4) * 4, &g_Q16[(qrowbase + r) * 32 + c4 * 4]);
    }
    #pragma unroll
    for (int i = 0; i < 4; i++) {
        int u = tid + i * 128;
        int r = u >> 3, cc = u & 7;
        unsigned d = sb + (r * 40 + cc * 4) * 4;
        cp16(d,         &g_K16[(kbase + kstart + r) * 32 + cc * 4]);
        cp16(d + 10240, &g_Vt16[(vbase + r) * (T / 2) + (kstart >> 1) + cc * 4]);
    }
    CP_COMMIT();                 // G0: Q + tile0
    #pragma unroll
    for (int i = 0; i < 4; i++) {
        int u = tid + i * 128;
        int r = u >> 3, cc = u & 7;
        unsigned d = sb + (5120 + r * 40 + cc * 4) * 4;
        cp16(d,         &g_K16[(kbase + kstart + 64 + r) * 32 + cc * 4]);
        cp16(d + 10240, &g_Vt16[(vbase + r) * (T / 2) + ((kstart + 64) >> 1) + cc * 4]);
    }
    CP_COMMIT();                 // G1: tile1
    CP_WAIT_1();                 // G0 complete
    __syncthreads();

    float sA[8][4], sB[8][4];
    qk_phase(sm, Qst, rA0, rA1, rB0, rB1, g, j, sA, sB);   // QK(tile0)

    float oA[8][4], oB[8][4], olA[4], olB[4];
    #pragma unroll
    for (int n = 0; n < 8; n++)
        #pragma unroll
        for (int i = 0; i < 4; i++) { oA[n][i] = 0.f; oB[n][i] = 0.f; }
    #pragma unroll
    for (int i = 0; i < 4; i++) { olA[i] = 0.f; olB[i] = 0.f; }

    const int gr0 = qs + rA0;
    const int wmin = qs + base;
    const unsigned ONE2 = 0x3C003C00u;
    unsigned paA[4][4], paB[4][4];

    for (int t = 0; t < nt; t++) {
        const int kt = kstart + t * KT2;
        const bool act = (kt <= wmin + 31);

        // ---- exp/mask (t): register-only ----
        if (act) {
            if (kt + KT2 - 1 > wmin) {
                #pragma unroll
                for (int n = 0; n < 8; n++) {
                    int col = kt + n * 8 + 2 * j;
                    if (col     > gr0     ) sA[n][0] = -1e4f;
                    if (col + 1 > gr0     ) sA[n][1] = -1e4f;
                    if (col     > gr0 +  8) sA[n][2] = -1e4f;
                    if (col + 1 > gr0 +  8) sA[n][3] = -1e4f;
                    if (col     > gr0 + 16) sB[n][0] = -1e4f;
                    if (col + 1 > gr0 + 16) sB[n][1] = -1e4f;
                    if (col     > gr0 + 24) sB[n][2] = -1e4f;
                    if (col + 1 > gr0 + 24) sB[n][3] = -1e4f;
                }
            }
            #pragma unroll
            for (int n = 0; n < 8; n++) {
                int kk = n >> 1, hf = (n & 1) * 2;
                paA[kk][hf]     = h2exp2(pack_h2(sA[n][0], sA[n][1]));
                paA[kk][hf + 1] = h2exp2(pack_h2(sA[n][2], sA[n][3]));
                paB[kk][hf]     = h2exp2(pack_h2(sB[n][0], sB[n][1]));
                paB[kk][hf + 1] = h2exp2(pack_h2(sB[n][2], sB[n][3]));
            }
        }

        if (t + 1 < nt) {
            CP_WAIT_ALL();       // tile t+1 landed
            __syncthreads();
            if (t + 2 < nt) {    // prefetch t+2 into the dead buffer
                int nb = (t + 2) % 3;
                int ktn = kt + 2 * KT2;
                #pragma unroll
                for (int i = 0; i < 4; i++) {
                    int u = tid + i * 128;
                    int r = u >> 3, cc = u & 7;
                    unsigned d = sb + (nb * 5120 + r * 40 + cc * 4) * 4;
                    cp16(d,         &g_K16[(kbase + ktn + r) * 32 + cc * 4]);
                    cp16(d + 10240, &g_Vt16[(vbase + r) * (T / 2) + (ktn >> 1) + cc * 4]);
                }
                CP_COMMIT();
            }
            if (kt + KT2 <= wmin + 31)
                qk_phase(sm + ((t + 1) % 3) * 5120, Qst,
                         rA0, rA1, rB0, rB1, g, j, sA, sB);
        }

        // ---- PV(t) ----
        if (act) {
            const unsigned* Vts = sm + (t % 3) * 5120 + 2560;
            #pragma unroll
            for (int kk = 0; kk < 4; kk++) {
                #pragma unroll
                for (int nn = 0; nn < 8; nn++) {
                    uint2 bb = *(const uint2*)&Vts[(nn * 8 + g) * 40 + kk * 8 + 2 * j];
                    mma_f16(oA[nn], paA[kk], bb.x, bb.y);
                    mma_f16(oB[nn], paB[kk], bb.x, bb.y);
                }
                mma_f16(olA, paA[kk], ONE2, ONE2);
                mma_f16(olB, paB[kk], ONE2, ONE2);
            }
        }
    }

    // ---- epilogue: fp32 atomic accumulation into d_out (+ l into g_L32) ----
    float* outp = out + (size_t)(b * T + qs) * H;
    #pragma unroll
    for (int n = 0; n < 8; n++) {
        int d0 = n * 8 + 2 * j;
        atomicAdd(&outp[(size_t)rA0 * H + d0],     oA[n][0]);
        atomicAdd(&outp[(size_t)rA0 * H + d0 + 1], oA[n][1]);
        atomicAdd(&outp[(size_t)rA1 * H + d0],     oA[n][2]);
        atomicAdd(&outp[(size_t)rA1 * H + d0 + 1], oA[n][3]);
        atomicAdd(&outp[(size_t)rB0 * H + d0],     oB[n][0]);
        atomicAdd(&outp[(size_t)rB0 * H + d0 + 1], oB[n][1]);
        atomicAdd(&outp[(size_t)rB1 * H + d0],     oB[n][2]);
        atomicAdd(&outp[(size_t)rB1 * H + d0 + 1], oB[n][3]);
    }
    if (j == 0) {
        int rowg = b * T + qs;
        atomicAdd(&g_L32[rowg + rA0], olA[0]);
        atomicAdd(&g_L32[rowg + rA1], olA[2]);
        atomicAdd(&g_L32[rowg + rB0], olB[0]);
        atomicAdd(&g_L32[rowg + rB1], olB[2]);
    }
}

// ===================== Pass 3: normalize out by row sums ====================
__global__ __launch_bounds__(256) void normalize_kernel(float* __restrict__ out)
{
    int idx = blockIdx.x * 256 + threadIdx.x;    // per float4; 262144 total
    int qg = idx >> 4;
    float inv = 1.0f / g_L32[qg];
    float4 v = ((const float4*)out)[idx];
    ((float4*)out)[idx] = make_float4(v.x * inv, v.y * inv, v.z * inv, v.w * inv);
}

// ================================ launcher ==================================
extern "C" void kernel_launch(void* const* d_in, const int* in_sizes, int n_in,
                              void* d_out, int out_size)
{
    const float* x  = (const float*)d_in[0];
    const float* Wq = (const float*)d_in[1];
    const float* Wk = (const float*)d_in[2];
    const float* Wv = (const float*)d_in[3];

    cudaFuncSetAttribute(attn_f16, cudaFuncAttributeMaxDynamicSharedMemorySize,
                         ATTN_SMEM_B);

    zero_kernel<<<1024, 256>>>((float*)d_out);
    wt_split<<<(NQK * WROW + 255) / 256, 256>>>(Wq, Wk, Wv);
    qkv_mma<<<NROWS / 64, 256>>>(x);
    attn_f16<<<dim3(B, NBLK), 128, ATTN_SMEM_B>>>((float*)d_out);
    normalize_kernel<<<1024, 256>>>((float*)d_out);
}

// round 16
// speedup vs baseline: 1.2717x; 1.1140x over previous
#include <cuda_runtime.h>
#include <cuda_fp16.h>
#include <math.h>

// Problem constants
#define B 4
#define T 4096
#define E 204
#define H 64
#define NROWS (B*T)          // 16384
#define SCALE2 (0.07001400420140049f * 1.4426950408889634f)  // 1/sqrt(204) * log2(e)

// QKV tiling: K padded to 208 = 13 chunks of 16
#define NQK 192              // Q|K|V output cols
#define WROW 104             // u32 per W16 row (208 dims / 2)

// Attention tiling
#define QT 128               // queries per block (4 warps x 32 rows)
#define KT2 64               // keys per smem tile
#define CH 512               // split-K chunk
#define NCH (T/CH)           // 8
#define NST (T/QT)           // 32
#define NBLK 144             // active blocks per batch

// attn smem (u32): 3 K/V buffers of 5120 (K 2560 | V 2560), Q at 15360 [128][36]
#define QST_OFF 15360
#define ATTN_SMEM_B ((QST_OFF + 128*36) * 4)   // 79872 bytes

// ---------------- static scratch (no allocation allowed) ----------------
__device__ unsigned g_W16h[NQK*WROW];            // W^T fp16x2, B-frag interleave
__device__ unsigned g_Q16[(size_t)NROWS*32];     // Q fp16x2, pre-scaled by SCALE2
__device__ unsigned g_K16[(size_t)NROWS*32];     // K fp16x2, dim-interleaved
__device__ unsigned g_Vt16[(size_t)B*H*(T/2)];   // V^T fp16x2 [b][h][t], t-interleaved
__device__ unsigned g_Op16[(size_t)B*NST*NCH*QT*32];  // partial O, fp16x2
__device__ float g_Lp[B*NST*NCH*QT];             // partial row-sum (fp32)

// ---------------- helpers ----------------
__device__ __forceinline__ void mma_f16(float* d, const unsigned* a,
                                        unsigned b0, unsigned b1) {
    asm volatile(
        "mma.sync.aligned.m16n8k16.row.col.f32.f16.f16.f32 "
        "{%0,%1,%2,%3}, {%4,%5,%6,%7}, {%8,%9}, {%0,%1,%2,%3};\n"
        : "+f"(d[0]), "+f"(d[1]), "+f"(d[2]), "+f"(d[3])
        : "r"(a[0]), "r"(a[1]), "r"(a[2]), "r"(a[3]), "r"(b0), "r"(b1));
}

__device__ __forceinline__ unsigned pack_h2(float a, float b) {
    __half2 h = __floats2half2_rn(a, b);
    return *reinterpret_cast<unsigned*>(&h);
}

// fp16 hi/lo split of a float pair, packed fp16x2
__device__ __forceinline__ void split2(float a, float b, unsigned &hi, unsigned &lo) {
    __half2 h2 = __floats2half2_rn(a, b);
    float ar = a - __half2float(h2.x);
    float br = b - __half2float(h2.y);
    __half2 l2 = __floats2half2_rn(ar, br);
    hi = *reinterpret_cast<unsigned*>(&h2);
    lo = *reinterpret_cast<unsigned*>(&l2);
}

__device__ __forceinline__ unsigned h2exp2(unsigned x) {
    unsigned y;
    asm("ex2.approx.f16x2 %0, %1;" : "=r"(y) : "r"(x));
    return y;
}

__device__ __forceinline__ unsigned smem_u32(const void* p) {
    unsigned a;
    asm("{ .reg .u64 t; cvta.to.shared.u64 t, %1; cvt.u32.u64 %0, t; }" : "=r"(a) : "l"(p));
    return a;
}

__device__ __forceinline__ void cp16(unsigned dst, const void* src) {
    asm volatile("cp.async.cg.shared.global [%0], [%1], 16;" :: "r"(dst), "l"(src));
}
#define CP_COMMIT()  asm volatile("cp.async.commit_group;" ::: "memory")
#define CP_WAIT_ALL() asm volatile("cp.async.wait_group 0;" ::: "memory")
#define CP_WAIT_1()  asm volatile("cp.async.wait_group 1;" ::: "memory")

// u32 slot within a row for even dim d: per-16 group [p0 p4 p1 p5 p2 p6 p3 p7]
__device__ __forceinline__ int ileave_u32(int d) {
    return (d >> 4) * 8 + ((d & 7) >> 1) * 2 + (((d & 15) >= 8) ? 1 : 0);
}

// ====== Pass 0: W^T -> fp16 (hi only), B-fragment interleaved, coalesced ====
// n runs fastest: consecutive threads read consecutive W columns (coalesced).
__global__ __launch_bounds__(256) void wt_split(
    const float* __restrict__ Wq, const float* __restrict__ Wk,
    const float* __restrict__ Wv)
{
    int idx = blockIdx.x * 256 + threadIdx.x;
    if (idx >= NQK * WROW) return;
    int cpos = idx / NQK, n = idx % NQK;
    int ks = cpos >> 3, cw = cpos & 7;
    int d0 = 16 * ks + ((cw >> 1) << 1) + ((cw & 1) ? 8 : 0);
    const float* W = (n < 64) ? Wq : (n < 128) ? Wk : Wv;
    int col = n & 63;
    float v0 = (d0     < E) ? W[d0 * H + col]       : 0.f;
    float v1 = (d0 + 1 < E) ? W[(d0 + 1) * H + col] : 0.f;
    g_W16h[n * WROW + cpos] = pack_h2(v0, v1);
}

// ========= Pass 1: QKV projection via 2-term fp16 m16n8k16 =================
// acc = xh*Wh + xl*Wh  (x exact to ~2^-22; W carries one fp16 rounding —
// outputs are rounded to fp16 downstream anyway).
__global__ __launch_bounds__(256) void qkv_mma(const float* __restrict__ x)
{
    __shared__ unsigned qsm[3072];        // 12 KB multi-purpose
    unsigned* s_wh = qsm;                 // [192][8]
    unsigned* s_xh = qsm + 1536;          // [64][12]
    unsigned* s_xl = qsm + 2304;          // [64][12]

    const int tid = threadIdx.x;
    const int w = tid >> 5, lane = tid & 31;
    const int g = lane >> 2, j = lane & 3;
    const int rw = w >> 1, ch = w & 1;
    const int row0 = blockIdx.x * 64;
    const int r0 = rw * 16 + g, r1 = r0 + 8;

    float acc[12][4];
    #pragma unroll
    for (int nt = 0; nt < 12; nt++)
        #pragma unroll
        for (int i = 0; i < 4; i++) acc[nt][i] = 0.f;

    for (int kc = 0; kc < 208; kc += 16) {
        __syncthreads();
        // x chunk (64 x 16): split to fp16 hi/lo pairs
        #pragma unroll
        for (int i = 0; i < 2; i++) {
            int u = tid + i * 256;               // 0..511
            int r = u >> 3, cc = u & 7;
            int k = kc + 2 * cc;
            float v0 = 0.f, v1 = 0.f;
            if (k + 1 < E) {
                float2 t = *(const float2*)&x[(size_t)(row0 + r) * E + k];
                v0 = t.x; v1 = t.y;
            } else if (k < E) {
                v0 = x[(size_t)(row0 + r) * E + k];
            }
            unsigned hi, lo;
            split2(v0, v1, hi, lo);
            s_xh[r * 12 + cc] = hi;
            s_xl[r * 12 + cc] = lo;
        }
        // W chunk (192 rows x 8 u32): straight uint4 copies, 384 total
        int ko = kc >> 1;
        {
            int idx = tid;                       // 0..255
            int n = idx >> 1, half = idx & 1;
            *(uint4*)&s_wh[n * 8 + half * 4] =
                *(const uint4*)&g_W16h[n * WROW + ko + half * 4];
            idx = tid + 256;                     // 256..511, keep < 384
            if (idx < 384) {
                n = idx >> 1; half = idx & 1;
                *(uint4*)&s_wh[n * 8 + half * 4] =
                    *(const uint4*)&g_W16h[n * WROW + ko + half * 4];
            }
        }
        __syncthreads();

        unsigned ah[4], al[4];
        ah[0] = s_xh[r0*12 + j];     ah[1] = s_xh[r1*12 + j];
        ah[2] = s_xh[r0*12 + j + 4]; ah[3] = s_xh[r1*12 + j + 4];
        al[0] = s_xl[r0*12 + j];     al[1] = s_xl[r1*12 + j];
        al[2] = s_xl[r0*12 + j + 4]; al[3] = s_xl[r1*12 + j + 4];
        #pragma unroll
        for (int nt = 0; nt < 12; nt++) {
            int rb = ch * 96 + nt * 8 + g;
            uint2 bh = *(uint2*)&s_wh[rb * 8 + 2 * j];
            mma_f16(acc[nt], ah, bh.x, bh.y);
            mma_f16(acc[nt], al, bh.x, bh.y);
        }
    }
    __syncthreads();   // reuse qsm as V staging (need 64x66 floats = 16.5KB > 12KB)

    // stage V through a dedicated static smem block instead
    __shared__ float Vsm[64][66];
    const int b = row0 >> 12;
    const int t0 = row0 & (T - 1);
    const size_t R0g = row0 + r0, R1g = row0 + r1;

    #pragma unroll
    for (int nt = 0; nt < 12; nt++) {
        int c0 = ch * 96 + nt * 8 + 2 * j;
        float2 v0 = make_float2(acc[nt][0], acc[nt][1]);
        float2 v1 = make_float2(acc[nt][2], acc[nt][3]);
        if (c0 < 64) {
            g_Q16[R0g * 32 + (c0 >> 1)] = pack_h2(v0.x * SCALE2, v0.y * SCALE2);
            g_Q16[R1g * 32 + (c0 >> 1)] = pack_h2(v1.x * SCALE2, v1.y * SCALE2);
        } else if (c0 < 128) {
            int ui = ileave_u32(c0 - 64);
            g_K16[R0g * 32 + ui] = pack_h2(v0.x, v0.y);
            g_K16[R1g * 32 + ui] = pack_h2(v1.x, v1.y);
        } else {
            *(float2*)&Vsm[r0][c0 - 128] = v0;
            *(float2*)&Vsm[r1][c0 - 128] = v1;
        }
    }
    __syncthreads();
    {
        int tl2 = (tid & 31) * 2;
        int h0 = (tid >> 5) * 8;
        #pragma unroll
        for (int i = 0; i < 8; i++) {
            int h = h0 + i;
            unsigned pv = pack_h2(Vsm[tl2][h], Vsm[tl2 + 1][h]);
            int t = t0 + tl2;
            size_t ui = ((size_t)b * H + h) * (T / 2) + ileave_u32(t & 15)
                      + ((t >> 4) * 8);
            g_Vt16[ui] = pv;
        }
    }
}

// ---------------- attention QK phase ----------------
__device__ __forceinline__ void qk_phase(
    const unsigned* __restrict__ Ks, const unsigned* __restrict__ Qst,
    int rA0, int rA1, int rB0, int rB1, int g, int j,
    float sA[8][4], float sB[8][4])
{
    #pragma unroll
    for (int n = 0; n < 8; n++)
        #pragma unroll
        for (int i = 0; i < 4; i++) { sA[n][i] = 0.f; sB[n][i] = 0.f; }
    #pragma unroll
    for (int ks = 0; ks < 4; ks++) {
        unsigned aA[4], aB[4];
        aA[0] = Qst[rA0 * 36 + 8 * ks + j];
        aA[1] = Qst[rA1 * 36 + 8 * ks + j];
        aA[2] = Qst[rA0 * 36 + 8 * ks + j + 4];
        aA[3] = Qst[rA1 * 36 + 8 * ks + j + 4];
        aB[0] = Qst[rB0 * 36 + 8 * ks + j];
        aB[1] = Qst[rB1 * 36 + 8 * ks + j];
        aB[2] = Qst[rB0 * 36 + 8 * ks + j + 4];
        aB[3] = Qst[rB1 * 36 + 8 * ks + j + 4];
        #pragma unroll
        for (int n = 0; n < 8; n++) {
            uint2 bb = *(const uint2*)&Ks[(n * 8 + g) * 40 + ks * 8 + 2 * j];
            mma_f16(sA[n], aA, bb.x, bb.y);
            mma_f16(sB[n], aB, bb.x, bb.y);
        }
    }
}

// ============== Pass 2: pipelined split-K flash attention ==================
// (identical to the proven 54.0us R12 kernel)
__global__ __launch_bounds__(128, 2) void attn_f16()
{
    const int b = blockIdx.x;
    const int f = blockIdx.y;
    int s, c;
    if (f < 120) {               // full blocks (8 tiles)
        int rem = f, cc = 0;
        while (rem >= 29 - 4 * cc) { rem -= 29 - 4 * cc; cc++; }
        c = cc;
        s = 4 * c + 3 + rem;
    } else {                     // partial diagonal blocks, heaviest first
        int p = f - 120;
        int gq = p >> 3;
        int i = p & 7;
        s = 4 * i + (2 - gq);
        c = i;
    }
    const int qs = s * QT;
    const int kstart = c * CH;
    const int kend = min(kstart + CH, qs + QT);
    const int nt = (kend - kstart) >> 6;     // 2..8

    extern __shared__ unsigned sm[];
    const unsigned sb = smem_u32(sm);
    const unsigned* Qst = sm + QST_OFF;      // [128][36]

    const int tid = threadIdx.x;
    const int w = tid >> 5;
    const int lane = tid & 31;
    const int g = lane >> 2;
    const int j = lane & 3;
    const int base = w * 32;
    const int rA0 = base + g,  rA1 = rA0 + 8;
    const int rB0 = rA0 + 16,  rB1 = rA0 + 24;

    const size_t kbase = (size_t)b * T;
    const size_t vbase = (size_t)b * H;

    // ---- prologue: Q + tile0 (group 0), tile1 (group 1) ----
    const size_t qrowbase = kbase + qs;
    #pragma unroll
    for (int i = 0; i < 8; i++) {
        int u = tid + i * 128;
        int r = u >> 3, c4 = u & 7;
        cp16(sb + (QST_OFF + r * 36 + c4 * 4) * 4, &g_Q16[(qrowbase + r) * 32 + c4 * 4]);
    }
    #pragma unroll
    for (int i = 0; i < 4; i++) {
        int u = tid + i * 128;
        int r = u >> 3, cc = u & 7;
        unsigned d = sb + (r * 40 + cc * 4) * 4;
        cp16(d,         &g_K16[(kbase + kstart + r) * 32 + cc * 4]);
        cp16(d + 10240, &g_Vt16[(vbase + r) * (T / 2) + (kstart >> 1) + cc * 4]);
    }
    CP_COMMIT();                 // G0: Q + tile0
    #pragma unroll
    for (int i = 0; i < 4; i++) {
        int u = tid + i * 128;
        int r = u >> 3, cc = u & 7;
        unsigned d = sb + (5120 + r * 40 + cc * 4) * 4;
        cp16(d,         &g_K16[(kbase + kstart + 64 + r) * 32 + cc * 4]);
        cp16(d + 10240, &g_Vt16[(vbase + r) * (T / 2) + ((kstart + 64) >> 1) + cc * 4]);
    }
    CP_COMMIT();                 // G1: tile1
    CP_WAIT_1();                 // G0 complete
    __syncthreads();

    float sA[8][4], sB[8][4];
    qk_phase(sm, Qst, rA0, rA1, rB0, rB1, g, j, sA, sB);   // QK(tile0)

    float oA[8][4], oB[8][4], olA[4], olB[4];
    #pragma unroll
    for (int n = 0; n < 8; n++)
        #pragma unroll
        for (int i = 0; i < 4; i++) { oA[n][i] = 0.f; oB[n][i] = 0.f; }
    #pragma unroll
    for (int i = 0; i < 4; i++) { olA[i] = 0.f; olB[i] = 0.f; }

    const int gr0 = qs + rA0;
    const int wmin = qs + base;
    const unsigned ONE2 = 0x3C003C00u;
    unsigned paA[4][4], paB[4][4];

    for (int t = 0; t < nt; t++) {
        const int kt = kstart + t * KT2;
        const bool act = (kt <= wmin + 31);

        // ---- exp/mask (t): register-only ----
        if (act) {
            if (kt + KT2 - 1 > wmin) {
                #pragma unroll
                for (int n = 0; n < 8; n++) {
                    int col = kt + n * 8 + 2 * j;
                    if (col     > gr0     ) sA[n][0] = -1e4f;
                    if (col + 1 > gr0     ) sA[n][1] = -1e4f;
                    if (col     > gr0 +  8) sA[n][2] = -1e4f;
                    if (col + 1 > gr0 +  8) sA[n][3] = -1e4f;
                    if (col     > gr0 + 16) sB[n][0] = -1e4f;
                    if (col + 1 > gr0 + 16) sB[n][1] = -1e4f;
                    if (col     > gr0 + 24) sB[n][2] = -1e4f;
                    if (col + 1 > gr0 + 24) sB[n][3] = -1e4f;
                }
            }
            #pragma unroll
            for (int n = 0; n < 8; n++) {
                int kk = n >> 1, hf = (n & 1) * 2;
                paA[kk][hf]     = h2exp2(pack_h2(sA[n][0], sA[n][1]));
                paA[kk][hf + 1] = h2exp2(pack_h2(sA[n][2], sA[n][3]));
                paB[kk][hf]     = h2exp2(pack_h2(sB[n][0], sB[n][1]));
                paB[kk][hf + 1] = h2exp2(pack_h2(sB[n][2], sB[n][3]));
            }
        }

        if (t + 1 < nt) {
            CP_WAIT_ALL();       // tile t+1 landed
            __syncthreads();
            if (t + 2 < nt) {    // prefetch t+2 into the dead buffer
                int nb = (t + 2) % 3;
                int ktn = kt + 2 * KT2;
                #pragma unroll
                for (int i = 0; i < 4; i++) {
                    int u = tid + i * 128;
                    int r = u >> 3, cc = u & 7;
                    unsigned d = sb + (nb * 5120 + r * 40 + cc * 4) * 4;
                    cp16(d,         &g_K16[(kbase + ktn + r) * 32 + cc * 4]);
                    cp16(d + 10240, &g_Vt16[(vbase + r) * (T / 2) + (ktn >> 1) + cc * 4]);
                }
                CP_COMMIT();
            }
            if (kt + KT2 <= wmin + 31)
                qk_phase(sm + ((t + 1) % 3) * 5120, Qst,
                         rA0, rA1, rB0, rB1, g, j, sA, sB);
        }

        // ---- PV(t) ----
        if (act) {
            const unsigned* Vts = sm + (t % 3) * 5120 + 2560;
            #pragma unroll
            for (int kk = 0; kk < 4; kk++) {
                #pragma unroll
                for (int nn = 0; nn < 8; nn++) {
                    uint2 bb = *(const uint2*)&Vts[(nn * 8 + g) * 40 + kk * 8 + 2 * j];
                    mma_f16(oA[nn], paA[kk], bb.x, bb.y);
                    mma_f16(oB[nn], paB[kk], bb.x, bb.y);
                }
                mma_f16(olA, paA[kk], ONE2, ONE2);
                mma_f16(olB, paB[kk], ONE2, ONE2);
            }
        }
    }

    // ---- write partials ----
    size_t pbase = (((size_t)(b * NST + s) * NCH + c) * QT);
    #pragma unroll
    for (int n = 0; n < 8; n++) {
        g_Op16[(pbase + rA0) * 32 + n * 4 + j] = pack_h2(oA[n][0], oA[n][1]);
        g_Op16[(pbase + rA1) * 32 + n * 4 + j] = pack_h2(oA[n][2], oA[n][3]);
        g_Op16[(pbase + rB0) * 32 + n * 4 + j] = pack_h2(oB[n][0], oB[n][1]);
        g_Op16[(pbase + rB1) * 32 + n * 4 + j] = pack_h2(oB[n][2], oB[n][3]);
    }
    if (j == 0) {
        g_Lp[pbase + rA0] = olA[0];
        g_Lp[pbase + rA1] = olA[2];
        g_Lp[pbase + rB0] = olB[0];
        g_Lp[pbase + rB1] = olB[2];
    }
}

// ===================== Pass 3: combine split-K partials =====================
__global__ __launch_bounds__(256) void combine_kernel(float* __restrict__ out)
{
    int idx = blockIdx.x * 256 + threadIdx.x;
    if (idx >= B * T * 16) return;
    int h4 = idx & 15;
    int qg = idx >> 4;
    int b  = qg >> 12;
    int q  = qg & (T - 1);
    int s  = q >> 7;
    int ql = q & (QT - 1);
    int cmax = q >> 9;

    size_t base = ((size_t)(b * NST + s) * NCH) * QT + ql;

    float L = 0.f;
    float acc[4];
    #pragma unroll
    for (int i = 0; i < 4; i++) acc[i] = 0.f;

    for (int cc = 0; cc <= cmax; cc++) {
        size_t pi = base + (size_t)cc * QT;
        L += g_Lp[pi];
        uint2 v = *(const uint2*)&g_Op16[pi * 32 + h4 * 2];
        float2 f0 = __half22float2(*reinterpret_cast<__half2*>(&v.x));
        float2 f1 = __half22float2(*reinterpret_cast<__half2*>(&v.y));
        acc[0] += f0.x; acc[1] += f0.y;
        acc[2] += f1.x; acc[3] += f1.y;
    }
    float inv = 1.0f / L;
    *(float4*)(out + (size_t)qg * H + h4 * 4) =
        make_float4(acc[0] * inv, acc[1] * inv, acc[2] * inv, acc[3] * inv);
}

// ================================ launcher ==================================
extern "C" void kernel_launch(void* const* d_in, const int* in_sizes, int n_in,
                              void* d_out, int out_size)
{
    const float* x  = (const float*)d_in[0];
    const float* Wq = (const float*)d_in[1];
    const float* Wk = (const float*)d_in[2];
    const float* Wv = (const float*)d_in[3];

    cudaFuncSetAttribute(attn_f16, cudaFuncAttributeMaxDynamicSharedMemorySize,
                         ATTN_SMEM_B);

    wt_split<<<(NQK * WROW + 255) / 256, 256>>>(Wq, Wk, Wv);
    qkv_mma<<<NROWS / 64, 256>>>(x);
    attn_f16<<<dim3(B, NBLK), 128, ATTN_SMEM_B>>>();
    combine_kernel<<<(B * T * 16 + 255) / 256, 256>>>((float*)d_out);
}

// round 17
// speedup vs baseline: 1.2812x; 1.0074x over previous
#include <cuda_runtime.h>
#include <cuda_fp16.h>
#include <math.h>

// Problem constants
#define B 4
#define T 4096
#define E 204
#define H 64
#define NROWS (B*T)          // 16384
#define SCALE2 (0.07001400420140049f * 1.4426950408889634f)  // 1/sqrt(204) * log2(e)

// QKV tiling: K padded to 208 = 13 chunks of 16
#define NQK 192              // Q|K|V output cols
#define WROW 104             // u32 per W16 row (208 dims / 2)

// Attention tiling
#define QT 128               // queries per block (4 warps x 32 rows)
#define KT2 64               // keys per smem tile
#define CH 512               // split-K chunk
#define NCH (T/CH)           // 8
#define NST (T/QT)           // 32
#define NBLK 144             // active blocks per batch

// attn smem (u32): 3 K/V buffers of 5120 (K 2560 | V 2560), Q at 15360 [128][36]
#define QST_OFF 15360
#define ATTN_SMEM_B ((QST_OFF + 128*36) * 4)   // 79872 bytes

// ---------------- static scratch (no allocation allowed) ----------------
__device__ unsigned g_W16h[NQK*WROW];            // W^T fp16x2, B-frag interleave
__device__ unsigned g_Q16[(size_t)NROWS*32];     // Q fp16x2, pre-scaled by SCALE2
__device__ unsigned g_K16[(size_t)NROWS*32];     // K fp16x2, dim-interleaved
__device__ unsigned g_Vt16[(size_t)B*H*(T/2)];   // V^T fp16x2 [b][h][t], t-interleaved
__device__ unsigned g_Op16[(size_t)B*NST*NCH*QT*32];  // partial O, fp16x2
__device__ float g_Lp[B*NST*NCH*QT];             // partial row-sum (fp32)

// ---------------- helpers ----------------
__device__ __forceinline__ void mma_f16(float* d, const unsigned* a,
                                        unsigned b0, unsigned b1) {
    asm volatile(
        "mma.sync.aligned.m16n8k16.row.col.f32.f16.f16.f32 "
        "{%0,%1,%2,%3}, {%4,%5,%6,%7}, {%8,%9}, {%0,%1,%2,%3};\n"
        : "+f"(d[0]), "+f"(d[1]), "+f"(d[2]), "+f"(d[3])
        : "r"(a[0]), "r"(a[1]), "r"(a[2]), "r"(a[3]), "r"(b0), "r"(b1));
}

__device__ __forceinline__ unsigned pack_h2(float a, float b) {
    __half2 h = __floats2half2_rn(a, b);
    return *reinterpret_cast<unsigned*>(&h);
}

// fp16 hi/lo split of a float pair, packed fp16x2
__device__ __forceinline__ void split2(float a, float b, unsigned &hi, unsigned &lo) {
    __half2 h2 = __floats2half2_rn(a, b);
    float ar = a - __half2float(h2.x);
    float br = b - __half2float(h2.y);
    __half2 l2 = __floats2half2_rn(ar, br);
    hi = *reinterpret_cast<unsigned*>(&h2);
    lo = *reinterpret_cast<unsigned*>(&l2);
}

__device__ __forceinline__ unsigned h2exp2(unsigned x) {
    unsigned y;
    asm("ex2.approx.f16x2 %0, %1;" : "=r"(y) : "r"(x));
    return y;
}

__device__ __forceinline__ unsigned smem_u32(const void* p) {
    unsigned a;
    asm("{ .reg .u64 t; cvta.to.shared.u64 t, %1; cvt.u32.u64 %0, t; }" : "=r"(a) : "l"(p));
    return a;
}

__device__ __forceinline__ void cp16(unsigned dst, const void* src) {
    asm volatile("cp.async.cg.shared.global [%0], [%1], 16;" :: "r"(dst), "l"(src));
}
#define CP_COMMIT()  asm volatile("cp.async.commit_group;" ::: "memory")
#define CP_WAIT_ALL() asm volatile("cp.async.wait_group 0;" ::: "memory")
#define CP_WAIT_1()  asm volatile("cp.async.wait_group 1;" ::: "memory")

// u32 slot within a row for even dim d: per-16 group [p0 p4 p1 p5 p2 p6 p3 p7]
__device__ __forceinline__ int ileave_u32(int d) {
    return (d >> 4) * 8 + ((d & 7) >> 1) * 2 + (((d & 15) >= 8) ? 1 : 0);
}

// ====== Pass 0: W^T -> fp16 (hi only), B-fragment interleaved, coalesced ====
// n runs fastest: consecutive threads read consecutive W columns (coalesced).
__global__ __launch_bounds__(256) void wt_split(
    const float* __restrict__ Wq, const float* __restrict__ Wk,
    const float* __restrict__ Wv)
{
    int idx = blockIdx.x * 256 + threadIdx.x;
    if (idx >= NQK * WROW) return;
    int cpos = idx / NQK, n = idx % NQK;
    int ks = cpos >> 3, cw = cpos & 7;
    int d0 = 16 * ks + ((cw >> 1) << 1) + ((cw & 1) ? 8 : 0);
    const float* W = (n < 64) ? Wq : (n < 128) ? Wk : Wv;
    int col = n & 63;
    float v0 = (d0     < E) ? W[d0 * H + col]       : 0.f;
    float v1 = (d0 + 1 < E) ? W[(d0 + 1) * H + col] : 0.f;
    g_W16h[n * WROW + cpos] = pack_h2(v0, v1);
}

// ========= Pass 1: QKV projection via 2-term fp16 m16n8k16 =================
// acc = xh*Wh + xl*Wh  (x exact to ~2^-22; W carries one fp16 rounding —
// outputs are rounded to fp16 downstream anyway).
__global__ __launch_bounds__(256) void qkv_mma(const float* __restrict__ x)
{
    __shared__ unsigned qsm[3072];        // 12 KB multi-purpose
    unsigned* s_wh = qsm;                 // [192][8]
    unsigned* s_xh = qsm + 1536;          // [64][12]
    unsigned* s_xl = qsm + 2304;          // [64][12]

    const int tid = threadIdx.x;
    const int w = tid >> 5, lane = tid & 31;
    const int g = lane >> 2, j = lane & 3;
    const int rw = w >> 1, ch = w & 1;
    const int row0 = blockIdx.x * 64;
    const int r0 = rw * 16 + g, r1 = r0 + 8;

    float acc[12][4];
    #pragma unroll
    for (int nt = 0; nt < 12; nt++)
        #pragma unroll
        for (int i = 0; i < 4; i++) acc[nt][i] = 0.f;

    for (int kc = 0; kc < 208; kc += 16) {
        __syncthreads();
        // x chunk (64 x 16): split to fp16 hi/lo pairs
        #pragma unroll
        for (int i = 0; i < 2; i++) {
            int u = tid + i * 256;               // 0..511
            int r = u >> 3, cc = u & 7;
            int k = kc + 2 * cc;
            float v0 = 0.f, v1 = 0.f;
            if (k + 1 < E) {
                float2 t = *(const float2*)&x[(size_t)(row0 + r) * E + k];
                v0 = t.x; v1 = t.y;
            } else if (k < E) {
                v0 = x[(size_t)(row0 + r) * E + k];
            }
            unsigned hi, lo;
            split2(v0, v1, hi, lo);
            s_xh[r * 12 + cc] = hi;
            s_xl[r * 12 + cc] = lo;
        }
        // W chunk (192 rows x 8 u32): straight uint4 copies, 384 total
        int ko = kc >> 1;
        {
            int idx = tid;                       // 0..255
            int n = idx >> 1, half = idx & 1;
            *(uint4*)&s_wh[n * 8 + half * 4] =
                *(const uint4*)&g_W16h[n * WROW + ko + half * 4];
            idx = tid + 256;                     // 256..511, keep < 384
            if (idx < 384) {
                n = idx >> 1; half = idx & 1;
                *(uint4*)&s_wh[n * 8 + half * 4] =
                    *(const uint4*)&g_W16h[n * WROW + ko + half * 4];
            }
        }
        __syncthreads();

        unsigned ah[4], al[4];
        ah[0] = s_xh[r0*12 + j];     ah[1] = s_xh[r1*12 + j];
        ah[2] = s_xh[r0*12 + j + 4]; ah[3] = s_xh[r1*12 + j + 4];
        al[0] = s_xl[r0*12 + j];     al[1] = s_xl[r1*12 + j];
        al[2] = s_xl[r0*12 + j + 4]; al[3] = s_xl[r1*12 + j + 4];
        #pragma unroll
        for (int nt = 0; nt < 12; nt++) {
            int rb = ch * 96 + nt * 8 + g;
            uint2 bh = *(uint2*)&s_wh[rb * 8 + 2 * j];
            mma_f16(acc[nt], ah, bh.x, bh.y);
            mma_f16(acc[nt], al, bh.x, bh.y);
        }
    }
    __syncthreads();   // reuse qsm as V staging (need 64x66 floats = 16.5KB > 12KB)

    // stage V through a dedicated static smem block instead
    __shared__ float Vsm[64][66];
    const int b = row0 >> 12;
    const int t0 = row0 & (T - 1);
    const size_t R0g = row0 + r0, R1g = row0 + r1;

    #pragma unroll
    for (int nt = 0; nt < 12; nt++) {
        int c0 = ch * 96 + nt * 8 + 2 * j;
        float2 v0 = make_float2(acc[nt][0], acc[nt][1]);
        float2 v1 = make_float2(acc[nt][2], acc[nt][3]);
        if (c0 < 64) {
            g_Q16[R0g * 32 + (c0 >> 1)] = pack_h2(v0.x * SCALE2, v0.y * SCALE2);
            g_Q16[R1g * 32 + (c0 >> 1)] = pack_h2(v1.x * SCALE2, v1.y * SCALE2);
        } else if (c0 < 128) {
            int ui = ileave_u32(c0 - 64);
            g_K16[R0g * 32 + ui] = pack_h2(v0.x, v0.y);
            g_K16[R1g * 32 + ui] = pack_h2(v1.x, v1.y);
        } else {
            *(float2*)&Vsm[r0][c0 - 128] = v0;
            *(float2*)&Vsm[r1][c0 - 128] = v1;
        }
    }
    __syncthreads();
    {
        int tl2 = (tid & 31) * 2;
        int h0 = (tid >> 5) * 8;
        #pragma unroll
        for (int i = 0; i < 8; i++) {
            int h = h0 + i;
            unsigned pv = pack_h2(Vsm[tl2][h], Vsm[tl2 + 1][h]);
            int t = t0 + tl2;
            size_t ui = ((size_t)b * H + h) * (T / 2) + ileave_u32(t & 15)
                      + ((t >> 4) * 8);
            g_Vt16[ui] = pv;
        }
    }
}

// ---------------- attention QK phase ----------------
__device__ __forceinline__ void qk_phase(
    const unsigned* __restrict__ Ks, const unsigned* __restrict__ Qst,
    int rA0, int rA1, int rB0, int rB1, int g, int j,
    float sA[8][4], float sB[8][4])
{
    #pragma unroll
    for (int n = 0; n < 8; n++)
        #pragma unroll
        for (int i = 0; i < 4; i++) { sA[n][i] = 0.f; sB[n][i] = 0.f; }
    #pragma unroll
    for (int ks = 0; ks < 4; ks++) {
        unsigned aA[4], aB[4];
        aA[0] = Qst[rA0 * 36 + 8 * ks + j];
        aA[1] = Qst[rA1 * 36 + 8 * ks + j];
        aA[2] = Qst[rA0 * 36 + 8 * ks + j + 4];
        aA[3] = Qst[rA1 * 36 + 8 * ks + j + 4];
        aB[0] = Qst[rB0 * 36 + 8 * ks + j];
        aB[1] = Qst[rB1 * 36 + 8 * ks + j];
        aB[2] = Qst[rB0 * 36 + 8 * ks + j + 4];
        aB[3] = Qst[rB1 * 36 + 8 * ks + j + 4];
        #pragma unroll
        for (int n = 0; n < 8; n++) {
            uint2 bb = *(const uint2*)&Ks[(n * 8 + g) * 40 + ks * 8 + 2 * j];
            mma_f16(sA[n], aA, bb.x, bb.y);
            mma_f16(sB[n], aB, bb.x, bb.y);
        }
    }
}

// ============== Pass 2: pipelined split-K flash attention ==================
// (identical to the proven 54.0us R12 kernel)
__global__ __launch_bounds__(128, 2) void attn_f16()
{
    const int b = blockIdx.x;
    const int f = blockIdx.y;
    int s, c;
    if (f < 120) {               // full blocks (8 tiles)
        int rem = f, cc = 0;
        while (rem >= 29 - 4 * cc) { rem -= 29 - 4 * cc; cc++; }
        c = cc;
        s = 4 * c + 3 + rem;
    } else {                     // partial diagonal blocks, heaviest first
        int p = f - 120;
        int gq = p >> 3;
        int i = p & 7;
        s = 4 * i + (2 - gq);
        c = i;
    }
    const int qs = s * QT;
    const int kstart = c * CH;
    const int kend = min(kstart + CH, qs + QT);
    const int nt = (kend - kstart) >> 6;     // 2..8

    extern __shared__ unsigned sm[];
    const unsigned sb = smem_u32(sm);
    const unsigned* Qst = sm + QST_OFF;      // [128][36]

    const int tid = threadIdx.x;
    const int w = tid >> 5;
    const int lane = tid & 31;
    const int g = lane >> 2;
    const int j = lane & 3;
    const int base = w * 32;
    const int rA0 = base + g,  rA1 = rA0 + 8;
    const int rB0 = rA0 + 16,  rB1 = rA0 + 24;

    const size_t kbase = (size_t)b * T;
    const size_t vbase = (size_t)b * H;

    // ---- prologue: Q + tile0 (group 0), tile1 (group 1) ----
    const size_t qrowbase = kbase + qs;
    #pragma unroll
    for (int i = 0; i < 8; i++) {
        int u = tid + i * 128;
        int r = u >> 3, c4 = u & 7;
        cp16(sb + (QST_OFF + r * 36 + c4 * 4) * 4, &g_Q16[(qrowbase + r) * 32 + c4 * 4]);
    }
    #pragma unroll
    for (int i = 0; i < 4; i++) {
        int u = tid + i * 128;
        int r = u >> 3, cc = u & 7;
        unsigned d = sb + (r * 40 + cc * 4) * 4;
        cp16(d,         &g_K16[(kbase + kstart + r) * 32 + cc * 4]);
        cp16(d + 10240, &g_Vt16[(vbase + r) * (T / 2) + (kstart >> 1) + cc * 4]);
    }
    CP_COMMIT();                 // G0: Q + tile0
    #pragma unroll
    for (int i = 0; i < 4; i++) {
        int u = tid + i * 128;
        int r = u >> 3, cc = u & 7;
        unsigned d = sb + (5120 + r * 40 + cc * 4) * 4;
        cp16(d,         &g_K16[(kbase + kstart + 64 + r) * 32 + cc * 4]);
        cp16(d + 10240, &g_Vt16[(vbase + r) * (T / 2) + ((kstart + 64) >> 1) + cc * 4]);
    }
    CP_COMMIT();                 // G1: tile1
    CP_WAIT_1();                 // G0 complete
    __syncthreads();

    float sA[8][4], sB[8][4];
    qk_phase(sm, Qst, rA0, rA1, rB0, rB1, g, j, sA, sB);   // QK(tile0)

    float oA[8][4], oB[8][4], olA[4], olB[4];
    #pragma unroll
    for (int n = 0; n < 8; n++)
        #pragma unroll
        for (int i = 0; i < 4; i++) { oA[n][i] = 0.f; oB[n][i] = 0.f; }
    #pragma unroll
    for (int i = 0; i < 4; i++) { olA[i] = 0.f; olB[i] = 0.f; }

    const int gr0 = qs + rA0;
    const int wmin = qs + base;
    const unsigned ONE2 = 0x3C003C00u;
    unsigned paA[4][4], paB[4][4];

    for (int t = 0; t < nt; t++) {
        const int kt = kstart + t * KT2;
        const bool act = (kt <= wmin + 31);

        // ---- exp/mask (t): register-only ----
        if (act) {
            if (kt + KT2 - 1 > wmin) {
                #pragma unroll
                for (int n = 0; n < 8; n++) {
                    int col = kt + n * 8 + 2 * j;
                    if (col     > gr0     ) sA[n][0] = -1e4f;
                    if (col + 1 > gr0     ) sA[n][1] = -1e4f;
                    if (col     > gr0 +  8) sA[n][2] = -1e4f;
                    if (col + 1 > gr0 +  8) sA[n][3] = -1e4f;
                    if (col     > gr0 + 16) sB[n][0] = -1e4f;
                    if (col + 1 > gr0 + 16) sB[n][1] = -1e4f;
                    if (col     > gr0 + 24) sB[n][2] = -1e4f;
                    if (col + 1 > gr0 + 24) sB[n][3] = -1e4f;
                }
            }
            #pragma unroll
            for (int n = 0; n < 8; n++) {
                int kk = n >> 1, hf = (n & 1) * 2;
                paA[kk][hf]     = h2exp2(pack_h2(sA[n][0], sA[n][1]));
                paA[kk][hf + 1] = h2exp2(pack_h2(sA[n][2], sA[n][3]));
                paB[kk][hf]     = h2exp2(pack_h2(sB[n][0], sB[n][1]));
                paB[kk][hf + 1] = h2exp2(pack_h2(sB[n][2], sB[n][3]));
            }
        }

        if (t + 1 < nt) {
            CP_WAIT_ALL();       // tile t+1 landed
            __syncthreads();
            if (t + 2 < nt) {    // prefetch t+2 into the dead buffer
                int nb = (t + 2) % 3;
                int ktn = kt + 2 * KT2;
                #pragma unroll
                for (int i = 0; i < 4; i++) {
                    int u = tid + i * 128;
                    int r = u >> 3, cc = u & 7;
                    unsigned d = sb + (nb * 5120 + r * 40 + cc * 4) * 4;
                    cp16(d,         &g_K16[(kbase + ktn + r) * 32 + cc * 4]);
                    cp16(d + 10240, &g_Vt16[(vbase + r) * (T / 2) + (ktn >> 1) + cc * 4]);
                }
                CP_COMMIT();
            }
            if (kt + KT2 <= wmin + 31)
                qk_phase(sm + ((t + 1) % 3) * 5120, Qst,
                         rA0, rA1, rB0, rB1, g, j, sA, sB);
        }

        // ---- PV(t) ----
        if (act) {
            const unsigned* Vts = sm + (t % 3) * 5120 + 2560;
            #pragma unroll
            for (int kk = 0; kk < 4; kk++) {
                #pragma unroll
                for (int nn = 0; nn < 8; nn++) {
                    uint2 bb = *(const uint2*)&Vts[(nn * 8 + g) * 40 + kk * 8 + 2 * j];
                    mma_f16(oA[nn], paA[kk], bb.x, bb.y);
                    mma_f16(oB[nn], paB[kk], bb.x, bb.y);
                }
                mma_f16(olA, paA[kk], ONE2, ONE2);
                mma_f16(olB, paB[kk], ONE2, ONE2);
            }
        }
    }

    // ---- write partials ----
    size_t pbase = (((size_t)(b * NST + s) * NCH + c) * QT);
    #pragma unroll
    for (int n = 0; n < 8; n++) {
        g_Op16[(pbase + rA0) * 32 + n * 4 + j] = pack_h2(oA[n][0], oA[n][1]);
        g_Op16[(pbase + rA1) * 32 + n * 4 + j] = pack_h2(oA[n][2], oA[n][3]);
        g_Op16[(pbase + rB0) * 32 + n * 4 + j] = pack_h2(oB[n][0], oB[n][1]);
        g_Op16[(pbase + rB1) * 32 + n * 4 + j] = pack_h2(oB[n][2], oB[n][3]);
    }
    if (j == 0) {
        g_Lp[pbase + rA0] = olA[0];
        g_Lp[pbase + rA1] = olA[2];
        g_Lp[pbase + rB0] = olB[0];
        g_Lp[pbase + rB1] = olB[2];
    }
}

// ===================== Pass 3: combine split-K partials =====================
__global__ __launch_bounds__(256) void combine_kernel(float* __restrict__ out)
{
    int idx = blockIdx.x * 256 + threadIdx.x;
    if (idx >= B * T * 16) return;
    int h4 = idx & 15;
    int qg = idx >> 4;
    int b  = qg >> 12;
    int q  = qg & (T - 1);
    int s  = q >> 7;
    int ql = q & (QT - 1);
    int cmax = q >> 9;

    size_t base = ((size_t)(b * NST + s) * NCH) * QT + ql;

    float L = 0.f;
    float acc[4];
    #pragma unroll
    for (int i = 0; i < 4; i++) acc[i] = 0.f;

    for (int cc = 0; cc <= cmax; cc++) {
        size_t pi = base + (size_t)cc * QT;
        L += g_Lp[pi];
        uint2 v = *(const uint2*)&g_Op16[pi * 32 + h4 * 2];
        float2 f0 = __half22float2(*reinterpret_cast<__half2*>(&v.x));
        float2 f1 = __half22float2(*reinterpret_cast<__half2*>(&v.y));
        acc[0] += f0.x; acc[1] += f0.y;
        acc[2] += f1.x; acc[3] += f1.y;
    }
    float inv = 1.0f / L;
    *(float4*)(out + (size_t)qg * H + h4 * 4) =
        make_float4(acc[0] * inv, acc[1] * inv, acc[2] * inv, acc[3] * inv);
}

// ================================ launcher ==================================
extern "C" void kernel_launch(void* const* d_in, const int* in_sizes, int n_in,
                              void* d_out, int out_size)
{
    const float* x  = (const float*)d_in[0];
    const float* Wq = (const float*)d_in[1];
    const float* Wk = (const float*)d_in[2];
    const float* Wv = (const float*)d_in[3];

    cudaFuncSetAttribute(attn_f16, cudaFuncAttributeMaxDynamicSharedMemorySize,
                         ATTN_SMEM_B);

    wt_split<<<(NQK * WROW + 255) / 256, 256>>>(Wq, Wk, Wv);
    qkv_mma<<<NROWS / 64, 256>>>(x);
    attn_f16<<<dim3(B, NBLK), 128, ATTN_SMEM_B>>>();
    combine_kernel<<<(B * T * 16 + 255) / 256, 256>>>((float*)d_out);
}